// round 6
// baseline (speedup 1.0000x reference)
#include <cuda_runtime.h>
#include <cuda_fp16.h>
#include <cstdint>

#define BB 1024   // batch
#define DD 512    // latent dim
#define HH 1024   // MLP hidden
#define TT 64     // time points

// ---------------------------------------------------------------------------
// Persistent device state (no allocs allowed).
// ---------------------------------------------------------------------------
__device__ __align__(16) float g_z  [BB * DD];   // current z (fp32)
__device__ __align__(16) float g_acc[BB * DD];   // k1 + 2k2 + 2k3
__device__ __align__(16) __half g_zin[BB * DD];  // stage input (fp16)
__device__ __align__(16) __half g_h  [BB * HH];  // hidden activation (fp16)
__device__ __align__(16) __half g_W1h[DD * HH];
__device__ __align__(16) __half g_W2h[HH * DD];

// ---------------------------------------------------------------------------
// PTX helpers
// ---------------------------------------------------------------------------
__device__ __forceinline__ void cpa16(void* dst, const void* src) {
    uint32_t d = (uint32_t)__cvta_generic_to_shared(dst);
    asm volatile("cp.async.cg.shared.global [%0], [%1], 16;\n" :: "r"(d), "l"(src));
}
__device__ __forceinline__ void cp_commit() {
    asm volatile("cp.async.commit_group;\n" ::: "memory");
}
template <int N>
__device__ __forceinline__ void cp_wait() {
    asm volatile("cp.async.wait_group %0;\n" :: "n"(N) : "memory");
}
__device__ __forceinline__ void ldsm4(uint32_t* r, const __half* p) {
    uint32_t a = (uint32_t)__cvta_generic_to_shared(p);
    asm volatile("ldmatrix.sync.aligned.m8n8.x4.shared.b16 {%0,%1,%2,%3},[%4];\n"
                 : "=r"(r[0]), "=r"(r[1]), "=r"(r[2]), "=r"(r[3]) : "r"(a));
}
__device__ __forceinline__ void ldsm4t(uint32_t* r, const __half* p) {
    uint32_t a = (uint32_t)__cvta_generic_to_shared(p);
    asm volatile("ldmatrix.sync.aligned.m8n8.x4.trans.shared.b16 {%0,%1,%2,%3},[%4];\n"
                 : "=r"(r[0]), "=r"(r[1]), "=r"(r[2]), "=r"(r[3]) : "r"(a));
}
__device__ __forceinline__ void mma_f16(float* c, const uint32_t* a, uint32_t b0, uint32_t b1) {
    asm volatile("mma.sync.aligned.m16n8k16.row.col.f32.f16.f16.f32 "
                 "{%0,%1,%2,%3}, {%4,%5,%6,%7}, {%8,%9}, {%0,%1,%2,%3};\n"
                 : "+f"(c[0]), "+f"(c[1]), "+f"(c[2]), "+f"(c[3])
                 : "r"(a[0]), "r"(a[1]), "r"(a[2]), "r"(a[3]), "r"(b0), "r"(b1));
}

// ---------------------------------------------------------------------------
// Mainloop template.
// CTA tile 64(M) x 64(N); KG k-groups of 8 position-warps each.
// Position warp tile: 32(M) x 16(N)  [2m x 4n grid of warps].
// Buffer k-extent = KG*64; k-group g consumes k-slice [g*64, g*64+64).
// Threads = KG*256.  A: [M,KDIM] row-major fp16.  B: [KDIM,NDIM] row-major.
// Accum c[2][2][4] (m 2x16, n 2x8).
// ---------------------------------------------------------------------------
template <int KDIM, int NDIM, int KG>
__device__ __forceinline__ void mainloop(
    const __half* __restrict__ A, const __half* __restrict__ B,
    int m0, int n0, float c[2][2][4], char* smbase)
{
    constexpr int BK    = KG * 64;        // buffer k-extent
    constexpr int ASTR  = BK + 8;         // A row stride (halves)
    constexpr int BSTR  = 72;             // B row stride (halves)
    constexpr int ABYTE = 64 * ASTR * 2;
    constexpr int BBYTE = BK * BSTR * 2;
    constexpr int BUF   = ABYTE + BBYTE;
    constexpr int NT    = KDIM / BK;      // 8 for both gemms

    const int tid  = threadIdx.x;
    const int wid  = tid >> 5;
    const int lane = tid & 31;
    const int kg   = (KG == 2) ? (wid >> 3) : 0;
    const int pos  = wid & 7;
    const int wm = (pos & 1) * 32;
    const int wn = (pos >> 1) * 16;
    const int lr  = lane & 15;
    const int lc8 = (lane >> 4) * 8;

    auto sAp = [&](int b) { return (__half*)(smbase + b * BUF); };
    auto sBp = [&](int b) { return (__half*)(smbase + b * BUF + ABYTE); };

    // Loads: A has 64*BK/8 chunks, B has BK*64/8 chunks; threads = KG*256,
    // so each thread moves 2 A-chunks and 2 B-chunks.
    auto load_tile = [&](int it, int b) {
        const int kk = it * BK;
        __half* sA = sAp(b);
        __half* sB = sBp(b);
#pragma unroll
        for (int j = 0; j < 2; j++) {
            int ca = tid + j * (KG * 256);            // A chunk id
            int r  = ca / (KG * 8), cc = (ca % (KG * 8)) * 8;
            cpa16(sA + r * ASTR + cc, A + (size_t)(m0 + r) * KDIM + kk + cc);
            int cb = tid + j * (KG * 256);            // B chunk id
            int rb = cb >> 3, nb = (cb & 7) * 8;
            cpa16(sB + rb * BSTR + nb, B + (size_t)(kk + rb) * NDIM + n0 + nb);
        }
        cp_commit();
    };

    auto compute = [&](int b) {
        const __half* sA = sAp(b);
        const __half* sB = sBp(b);
#pragma unroll
        for (int s = 0; s < 4; s++) {
            const int kb = kg * 64 + s * 16;
            uint32_t av[2][4];
#pragma unroll
            for (int mt = 0; mt < 2; mt++)
                ldsm4(av[mt], sA + (wm + mt * 16 + lr) * ASTR + kb + lc8);
            uint32_t bv[4];
            ldsm4t(bv, sB + (kb + lr) * BSTR + wn + lc8);
#pragma unroll
            for (int mt = 0; mt < 2; mt++)
#pragma unroll
                for (int nt = 0; nt < 2; nt++)
                    mma_f16(c[mt][nt], av[mt], bv[nt * 2], bv[nt * 2 + 1]);
        }
    };

    load_tile(0, 0);
    load_tile(1, 1);
#pragma unroll 1
    for (int it = 0; it < NT; it++) {
        const int b = it % 3;
        cp_wait<1>();        // tile `it` resident (<=1 group pending)
        __syncthreads();     // all warps done with buffer (it+2)%3
        if (it + 2 < NT) load_tile(it + 2, (it + 2) % 3);
        compute(b);
    }
}

// ---------------------------------------------------------------------------
// GEMM1: h = tanh(zin @ W1 + b1) -> g_h.  grid (16,16), 256 thr, 54KB smem.
// ---------------------------------------------------------------------------
#define SMEM1 (3 * (64 * 72 * 2 + 64 * 72 * 2))        // 55296
__global__ void __launch_bounds__(256, 2) k_gemm1(const float* __restrict__ b1) {
    extern __shared__ __align__(16) char sm[];
    const int m0 = blockIdx.y * 64, n0 = blockIdx.x * 64;
    float c[2][2][4] = {};
    mainloop<DD, HH, 1>(g_zin, g_W1h, m0, n0, c, sm);

    const int wid = threadIdx.x >> 5, lane = threadIdx.x & 31;
    const int wm = (wid & 1) * 32, wn = (wid >> 1) * 16;
    const int er = lane >> 2, ec = (lane & 3) * 2;
#pragma unroll
    for (int mt = 0; mt < 2; mt++)
#pragma unroll
        for (int nt = 0; nt < 2; nt++) {
            int gn = n0 + wn + nt * 8 + ec;
            float bv0 = b1[gn], bv1 = b1[gn + 1];
#pragma unroll
            for (int h = 0; h < 2; h++) {
                int gm = m0 + wm + mt * 16 + er + h * 8;
                float v0 = tanhf(c[mt][nt][2 * h + 0] + bv0);
                float v1 = tanhf(c[mt][nt][2 * h + 1] + bv1);
                *reinterpret_cast<__half2*>(&g_h[(size_t)gm * HH + gn]) =
                    __halves2half2(__float2half(v0), __float2half(v1));
            }
        }
}

// ---------------------------------------------------------------------------
// GEMM2 + RK4 combine.  grid (8,16), 512 thr (2 k-groups), ~105KB smem.
// ---------------------------------------------------------------------------
#define SMEM2 (3 * (64 * 136 * 2 + 128 * 72 * 2))      // 107520
__global__ void __launch_bounds__(512, 1) k_gemm2(const float* __restrict__ b2,
                                                  const float* __restrict__ t,
                                                  int step, int stage,
                                                  float* __restrict__ traj) {
    extern __shared__ __align__(16) char sm[];
    const int m0 = blockIdx.y * 64, n0 = blockIdx.x * 64;
    float c[2][2][4] = {};
    mainloop<HH, DD, 2>(g_h, g_W2h, m0, n0, c, sm);

    const int tid = threadIdx.x, wid = tid >> 5, lane = tid & 31;
    const int kg = wid >> 3, pos = wid & 7;
    const int wm = (pos & 1) * 32, wn = (pos >> 1) * 16;
    const int er = lane >> 2, ec = (lane & 3) * 2;

    // Cross-k-group reduction via smem (reuse tile buffers).
    float* red = (float*)sm;                 // 64*64 fp32 = 16KB
    __syncthreads();                         // everyone done with tiles
    if (kg == 1) {
#pragma unroll
        for (int mt = 0; mt < 2; mt++)
#pragma unroll
            for (int nt = 0; nt < 2; nt++)
#pragma unroll
                for (int h = 0; h < 2; h++) {
                    int lm = wm + mt * 16 + er + h * 8;
                    int ln = wn + nt * 8 + ec;
                    *reinterpret_cast<float2*>(&red[lm * 64 + ln]) =
                        make_float2(c[mt][nt][2 * h], c[mt][nt][2 * h + 1]);
                }
    }
    __syncthreads();
    if (kg == 1) return;

    const float dt = t[step + 1] - t[step];
#pragma unroll
    for (int mt = 0; mt < 2; mt++)
#pragma unroll
        for (int nt = 0; nt < 2; nt++) {
            int gn = n0 + wn + nt * 8 + ec;
            float bv0 = b2[gn], bv1 = b2[gn + 1];
#pragma unroll
            for (int h = 0; h < 2; h++) {
                int lm = wm + mt * 16 + er + h * 8;
                int gm = m0 + lm;
                int idx = gm * DD + gn;
                float2 rv = *reinterpret_cast<const float2*>(&red[lm * 64 + wn + nt * 8 + ec]);
                float k0 = c[mt][nt][2 * h + 0] + rv.x + bv0;
                float k1 = c[mt][nt][2 * h + 1] + rv.y + bv1;
                float2 zv = *reinterpret_cast<const float2*>(&g_z[idx]);
                float zi0, zi1;
                if (stage == 0) {
                    *reinterpret_cast<float2*>(&g_acc[idx]) = make_float2(k0, k1);
                    zi0 = zv.x + 0.5f * dt * k0;
                    zi1 = zv.y + 0.5f * dt * k1;
                } else if (stage == 1) {
                    float2 a = *reinterpret_cast<const float2*>(&g_acc[idx]);
                    *reinterpret_cast<float2*>(&g_acc[idx]) =
                        make_float2(a.x + 2.f * k0, a.y + 2.f * k1);
                    zi0 = zv.x + 0.5f * dt * k0;
                    zi1 = zv.y + 0.5f * dt * k1;
                } else if (stage == 2) {
                    float2 a = *reinterpret_cast<const float2*>(&g_acc[idx]);
                    *reinterpret_cast<float2*>(&g_acc[idx]) =
                        make_float2(a.x + 2.f * k0, a.y + 2.f * k1);
                    zi0 = zv.x + dt * k0;
                    zi1 = zv.y + dt * k1;
                } else {
                    float2 a = *reinterpret_cast<const float2*>(&g_acc[idx]);
                    zi0 = zv.x + (dt * (1.0f / 6.0f)) * (a.x + k0);
                    zi1 = zv.y + (dt * (1.0f / 6.0f)) * (a.y + k1);
                    *reinterpret_cast<float2*>(&g_z[idx]) = make_float2(zi0, zi1);
                    *reinterpret_cast<float2*>(&traj[(size_t)(step + 1) * BB * DD + idx]) =
                        make_float2(zi0, zi1);
                }
                *reinterpret_cast<__half2*>(&g_zin[idx]) =
                    __halves2half2(__float2half(zi0), __float2half(zi1));
            }
        }
}

// ---------------------------------------------------------------------------
// Setup kernels
// ---------------------------------------------------------------------------
__global__ void convert_kernel(const float* __restrict__ src,
                               __half* __restrict__ dst, int n) {
    int i = blockIdx.x * 256 + threadIdx.x;
    if (i < n) dst[i] = __float2half(src[i]);
}

__global__ void init_kernel(const float* __restrict__ z0, float* __restrict__ traj) {
    int i = blockIdx.x * 256 + threadIdx.x;
    if (i < BB * DD) {
        float v = z0[i];
        g_z[i]   = v;
        traj[i]  = v;
        g_zin[i] = __float2half(v);
    }
}

// ---------------------------------------------------------------------------
extern "C" void kernel_launch(void* const* d_in, const int* in_sizes, int n_in,
                              void* d_out, int out_size) {
    const float* z0 = (const float*)d_in[0];
    const float* t  = (const float*)d_in[1];
    const float* W1 = (const float*)d_in[2];
    const float* b1 = (const float*)d_in[3];
    const float* W2 = (const float*)d_in[4];
    const float* b2 = (const float*)d_in[5];
    float* traj = (float*)d_out;

    __half *w1h, *w2h;
    cudaGetSymbolAddress((void**)&w1h, g_W1h);
    cudaGetSymbolAddress((void**)&w2h, g_W2h);

    cudaFuncSetAttribute(k_gemm1, cudaFuncAttributeMaxDynamicSharedMemorySize, SMEM1);
    cudaFuncSetAttribute(k_gemm2, cudaFuncAttributeMaxDynamicSharedMemorySize, SMEM2);

    convert_kernel<<<(DD * HH + 255) / 256, 256>>>(W1, w1h, DD * HH);
    convert_kernel<<<(HH * DD + 255) / 256, 256>>>(W2, w2h, HH * DD);
    init_kernel<<<(BB * DD + 255) / 256, 256>>>(z0, traj);

    dim3 grid1(HH / 64, BB / 64);   // 16 x 16 = 256 CTAs
    dim3 grid2(DD / 64, BB / 64);   // 8  x 16 = 128 CTAs

    for (int step = 0; step < TT - 1; step++) {
        for (int s = 0; s < 4; s++) {
            k_gemm1<<<grid1, 256, SMEM1>>>(b1);
            k_gemm2<<<grid2, 512, SMEM2>>>(b2, t, step, s, traj);
        }
    }
}

// round 7
// speedup vs baseline: 1.7332x; 1.7332x over previous
#include <cuda_runtime.h>
#include <cuda_fp16.h>
#include <cstdint>

#define BB 1024   // batch
#define DD 512    // latent dim
#define HH 1024   // MLP hidden
#define TT 64     // time points

// ---------------------------------------------------------------------------
// Persistent device state (no allocs allowed).
// ---------------------------------------------------------------------------
__device__ __align__(16) float g_z  [BB * DD];   // current z (fp32)
__device__ __align__(16) float g_acc[BB * DD];   // k1 + 2k2 + 2k3
__device__ __align__(16) __half g_zin[BB * DD];  // stage input (fp16)
__device__ __align__(16) __half g_h  [BB * HH];  // hidden activation (fp16)
__device__ __align__(16) __half g_W1h[DD * HH];
__device__ __align__(16) __half g_W2h[HH * DD];

// red tile: 64 rows x 68 floats (padded; 4-bank shift/row => conflict-free)
#define RSTR 68
#define RSZ  (64 * RSTR)

// ---------------------------------------------------------------------------
// PTX helpers
// ---------------------------------------------------------------------------
__device__ __forceinline__ void cpa16(void* dst, const void* src) {
    uint32_t d = (uint32_t)__cvta_generic_to_shared(dst);
    asm volatile("cp.async.cg.shared.global [%0], [%1], 16;\n" :: "r"(d), "l"(src));
}
__device__ __forceinline__ void cp_commit() {
    asm volatile("cp.async.commit_group;\n" ::: "memory");
}
template <int N>
__device__ __forceinline__ void cp_wait() {
    asm volatile("cp.async.wait_group %0;\n" :: "n"(N) : "memory");
}
__device__ __forceinline__ void ldsm4(uint32_t* r, const __half* p) {
    uint32_t a = (uint32_t)__cvta_generic_to_shared(p);
    asm volatile("ldmatrix.sync.aligned.m8n8.x4.shared.b16 {%0,%1,%2,%3},[%4];\n"
                 : "=r"(r[0]), "=r"(r[1]), "=r"(r[2]), "=r"(r[3]) : "r"(a));
}
__device__ __forceinline__ void ldsm4t(uint32_t* r, const __half* p) {
    uint32_t a = (uint32_t)__cvta_generic_to_shared(p);
    asm volatile("ldmatrix.sync.aligned.m8n8.x4.trans.shared.b16 {%0,%1,%2,%3},[%4];\n"
                 : "=r"(r[0]), "=r"(r[1]), "=r"(r[2]), "=r"(r[3]) : "r"(a));
}
__device__ __forceinline__ void mma_f16(float* c, const uint32_t* a, uint32_t b0, uint32_t b1) {
    asm volatile("mma.sync.aligned.m16n8k16.row.col.f32.f16.f16.f32 "
                 "{%0,%1,%2,%3}, {%4,%5,%6,%7}, {%8,%9}, {%0,%1,%2,%3};\n"
                 : "+f"(c[0]), "+f"(c[1]), "+f"(c[2]), "+f"(c[3])
                 : "r"(a[0]), "r"(a[1]), "r"(a[2]), "r"(a[3]), "r"(b0), "r"(b1));
}

// ---------------------------------------------------------------------------
// Mainloop: CTA tile 64x64, KG k-groups x 4 position-warps (warp tile 32x32).
// Buffer k-extent BK = KG*32; k-group kg consumes slice [kg*32, kg*32+32).
// Threads = KG*128.  A: [M,KDIM] row-major fp16.  B: [KDIM,NDIM] row-major.
// Partial sums end in c[2][4][4]; caller reduces across k-groups via smem.
// ---------------------------------------------------------------------------
template <int KDIM, int NDIM, int KG>
__device__ __forceinline__ void mainloop(
    const __half* __restrict__ A, const __half* __restrict__ B,
    int m0, int n0, float c[2][4][4], char* smbase)
{
    constexpr int BK    = KG * 32;
    constexpr int ASTR  = BK + 8;
    constexpr int BSTR  = 72;
    constexpr int ABYTE = 64 * ASTR * 2;
    constexpr int BBYTE = BK * BSTR * 2;
    constexpr int BUF   = ABYTE + BBYTE;
    constexpr int NT    = KDIM / BK;          // 8 for both gemms
    constexpr int NTHR  = KG * 128;

    const int tid  = threadIdx.x;
    const int wid  = tid >> 5;
    const int lane = tid & 31;
    const int kg   = wid >> 2;
    const int pos  = wid & 3;
    const int wm = (pos & 1) * 32;
    const int wn = (pos >> 1) * 32;
    const int lr  = lane & 15;
    const int lc8 = (lane >> 4) * 8;

    // Load mapping: 2 A-chunks + 2 B-chunks (16B) per thread per buffer.
    auto load_tile = [&](int it, int b) {
        const int kk = it * BK;
        __half* sA = (__half*)(smbase + b * BUF);
        __half* sB = (__half*)(smbase + b * BUF + ABYTE);
#pragma unroll
        for (int j = 0; j < 2; j++) {
            int ca = tid + j * NTHR;                       // A: 64 x (BK/8) chunks
            int r  = ca / (BK / 8), cc = (ca % (BK / 8)) * 8;
            cpa16(sA + r * ASTR + cc, A + (size_t)(m0 + r) * KDIM + kk + cc);
            int cb = tid + j * NTHR;                       // B: BK x 8 chunks
            int rb = cb >> 3, nb = (cb & 7) * 8;
            cpa16(sB + rb * BSTR + nb, B + (size_t)(kk + rb) * NDIM + n0 + nb);
        }
        cp_commit();
    };

    auto compute = [&](int b) {
        const __half* sA = (const __half*)(smbase + b * BUF);
        const __half* sB = (const __half*)(smbase + b * BUF + ABYTE);
        uint32_t av[2][2][4], bv[2][2][4];
#pragma unroll
        for (int s = 0; s < 2; s++) {                      // hoist all LDSM
            const int kb = kg * 32 + s * 16;
#pragma unroll
            for (int mt = 0; mt < 2; mt++)
                ldsm4(av[s][mt], sA + (wm + mt * 16 + lr) * ASTR + kb + lc8);
#pragma unroll
            for (int g = 0; g < 2; g++)
                ldsm4t(bv[s][g], sB + (kb + lr) * BSTR + wn + g * 16 + lc8);
        }
#pragma unroll
        for (int s = 0; s < 2; s++)
#pragma unroll
            for (int mt = 0; mt < 2; mt++)
#pragma unroll
                for (int nt = 0; nt < 4; nt++) {
                    const int g = nt >> 1, w = (nt & 1) * 2;
                    mma_f16(c[mt][nt], av[s][mt], bv[s][g][w], bv[s][g][w + 1]);
                }
    };

    load_tile(0, 0);
    load_tile(1, 1);
#pragma unroll 1
    for (int it = 0; it < NT; it++) {
        cp_wait<1>();        // tile `it` resident
        __syncthreads();     // all warps done with buffer (it+2)%3
        if (it + 2 < NT) load_tile(it + 2, (it + 2) % 3);
        compute(it % 3);
    }
    __syncthreads();         // tiles dead; smem reusable as reduction buffer

    // Dump this k-group's partials to its red region.
    float* red = (float*)smbase + kg * RSZ;
    const int er = lane >> 2, ec = (lane & 3) * 2;
#pragma unroll
    for (int mt = 0; mt < 2; mt++)
#pragma unroll
        for (int nt = 0; nt < 4; nt++)
#pragma unroll
            for (int h = 0; h < 2; h++) {
                int lm = wm + mt * 16 + er + h * 8;
                int ln = wn + nt * 8 + ec;
                *reinterpret_cast<float2*>(&red[lm * RSTR + ln]) =
                    make_float2(c[mt][nt][2 * h], c[mt][nt][2 * h + 1]);
            }
    __syncthreads();
}

// ---------------------------------------------------------------------------
// GEMM1: h = tanh(zin @ W1 + b1) -> g_h.  grid (16,16), 256 thr (KG=2).
// ---------------------------------------------------------------------------
#define SMEM1 (3 * (64 * 72 * 2 + 64 * 72 * 2))        // 55296
__global__ void __launch_bounds__(256, 2) k_gemm1(const float* __restrict__ b1) {
    extern __shared__ __align__(16) char sm[];
    const int m0 = blockIdx.y * 64, n0 = blockIdx.x * 64;
    float c[2][4][4] = {};
    mainloop<DD, HH, 2>(g_zin, g_W1h, m0, n0, c, sm);

    // Final pass: 256 threads x 8 float2 pairs over the 64x64 tile.
    const float* red = (const float*)sm;
    const int tid = threadIdx.x;
#pragma unroll
    for (int j = 0; j < 8; j++) {
        int p  = tid + j * 256;
        int lm = p >> 5, ln = (p & 31) * 2;
        float2 r0 = *reinterpret_cast<const float2*>(&red[lm * RSTR + ln]);
        float2 r1 = *reinterpret_cast<const float2*>(&red[RSZ + lm * RSTR + ln]);
        int gn = n0 + ln;
        float2 bv = *reinterpret_cast<const float2*>(&b1[gn]);
        float v0 = tanhf(r0.x + r1.x + bv.x);
        float v1 = tanhf(r0.y + r1.y + bv.y);
        *reinterpret_cast<__half2*>(&g_h[(size_t)(m0 + lm) * HH + gn]) =
            __halves2half2(__float2half(v0), __float2half(v1));
    }
}

// ---------------------------------------------------------------------------
// GEMM2 + RK4 combine.  grid (8,16), 512 thr (KG=4).
// ---------------------------------------------------------------------------
#define SMEM2 (3 * (64 * 136 * 2 + 128 * 72 * 2))      // 107520
__global__ void __launch_bounds__(512, 1) k_gemm2(const float* __restrict__ b2,
                                                  const float* __restrict__ t,
                                                  int step, int stage,
                                                  float* __restrict__ traj) {
    extern __shared__ __align__(16) char sm[];
    const int m0 = blockIdx.y * 64, n0 = blockIdx.x * 64;
    float c[2][4][4] = {};
    mainloop<HH, DD, 4>(g_h, g_W2h, m0, n0, c, sm);

    // Final pass: 512 threads x 4 float2 pairs over the 64x64 tile.
    const float* red = (const float*)sm;
    const float dt = t[step + 1] - t[step];
    const int tid = threadIdx.x;
#pragma unroll
    for (int j = 0; j < 4; j++) {
        int p  = tid + j * 512;
        int lm = p >> 5, ln = (p & 31) * 2;
        int off = lm * RSTR + ln;
        float2 r0 = *reinterpret_cast<const float2*>(&red[off]);
        float2 r1 = *reinterpret_cast<const float2*>(&red[RSZ + off]);
        float2 r2 = *reinterpret_cast<const float2*>(&red[2 * RSZ + off]);
        float2 r3 = *reinterpret_cast<const float2*>(&red[3 * RSZ + off]);
        int gn = n0 + ln;
        float2 bv = *reinterpret_cast<const float2*>(&b2[gn]);
        float k0 = r0.x + r1.x + r2.x + r3.x + bv.x;
        float k1 = r0.y + r1.y + r2.y + r3.y + bv.y;
        int idx = (m0 + lm) * DD + gn;
        float2 zv = *reinterpret_cast<const float2*>(&g_z[idx]);
        float zi0, zi1;
        if (stage == 0) {
            *reinterpret_cast<float2*>(&g_acc[idx]) = make_float2(k0, k1);
            zi0 = zv.x + 0.5f * dt * k0;
            zi1 = zv.y + 0.5f * dt * k1;
        } else if (stage == 1) {
            float2 a = *reinterpret_cast<const float2*>(&g_acc[idx]);
            *reinterpret_cast<float2*>(&g_acc[idx]) =
                make_float2(a.x + 2.f * k0, a.y + 2.f * k1);
            zi0 = zv.x + 0.5f * dt * k0;
            zi1 = zv.y + 0.5f * dt * k1;
        } else if (stage == 2) {
            float2 a = *reinterpret_cast<const float2*>(&g_acc[idx]);
            *reinterpret_cast<float2*>(&g_acc[idx]) =
                make_float2(a.x + 2.f * k0, a.y + 2.f * k1);
            zi0 = zv.x + dt * k0;
            zi1 = zv.y + dt * k1;
        } else {
            float2 a = *reinterpret_cast<const float2*>(&g_acc[idx]);
            zi0 = zv.x + (dt * (1.0f / 6.0f)) * (a.x + k0);
            zi1 = zv.y + (dt * (1.0f / 6.0f)) * (a.y + k1);
            *reinterpret_cast<float2*>(&g_z[idx]) = make_float2(zi0, zi1);
            *reinterpret_cast<float2*>(&traj[(size_t)(step + 1) * BB * DD + idx]) =
                make_float2(zi0, zi1);
        }
        *reinterpret_cast<__half2*>(&g_zin[idx]) =
            __halves2half2(__float2half(zi0), __float2half(zi1));
    }
}

// ---------------------------------------------------------------------------
// Setup kernels
// ---------------------------------------------------------------------------
__global__ void convert_kernel(const float* __restrict__ src,
                               __half* __restrict__ dst, int n) {
    int i = blockIdx.x * 256 + threadIdx.x;
    if (i < n) dst[i] = __float2half(src[i]);
}

__global__ void init_kernel(const float* __restrict__ z0, float* __restrict__ traj) {
    int i = blockIdx.x * 256 + threadIdx.x;
    if (i < BB * DD) {
        float v = z0[i];
        g_z[i]   = v;
        traj[i]  = v;
        g_zin[i] = __float2half(v);
    }
}

// ---------------------------------------------------------------------------
extern "C" void kernel_launch(void* const* d_in, const int* in_sizes, int n_in,
                              void* d_out, int out_size) {
    const float* z0 = (const float*)d_in[0];
    const float* t  = (const float*)d_in[1];
    const float* W1 = (const float*)d_in[2];
    const float* b1 = (const float*)d_in[3];
    const float* W2 = (const float*)d_in[4];
    const float* b2 = (const float*)d_in[5];
    float* traj = (float*)d_out;

    __half *w1h, *w2h;
    cudaGetSymbolAddress((void**)&w1h, g_W1h);
    cudaGetSymbolAddress((void**)&w2h, g_W2h);

    cudaFuncSetAttribute(k_gemm1, cudaFuncAttributeMaxDynamicSharedMemorySize, SMEM1);
    cudaFuncSetAttribute(k_gemm2, cudaFuncAttributeMaxDynamicSharedMemorySize, SMEM2);

    convert_kernel<<<(DD * HH + 255) / 256, 256>>>(W1, w1h, DD * HH);
    convert_kernel<<<(HH * DD + 255) / 256, 256>>>(W2, w2h, HH * DD);
    init_kernel<<<(BB * DD + 255) / 256, 256>>>(z0, traj);

    dim3 grid1(HH / 64, BB / 64);   // 16 x 16 = 256 CTAs
    dim3 grid2(DD / 64, BB / 64);   // 8  x 16 = 128 CTAs

    for (int step = 0; step < TT - 1; step++) {
        for (int s = 0; s < 4; s++) {
            k_gemm1<<<grid1, 256, SMEM1>>>(b1);
            k_gemm2<<<grid2, 512, SMEM2>>>(b2, t, step, s, traj);
        }
    }
}